// round 10
// baseline (speedup 1.0000x reference)
#include <cuda_runtime.h>
#include <cuda_bf16.h>
#include <cfloat>
#include <cstdint>

// Problem shape (fixed by the reference).
#define NB 32
#define TT 4000
#define DD 2048
#define RR 10

#define THREADS 256
#define MINBLOCKS 6          // caps regs at ~42 -> 6 blocks/SM
#define BLOCKS (152 * MINBLOCKS)   // one full wave on 152 SMs

// Per-(n,r) pooling slots. Order-preserving float->uint encoding; 0 acts as -inf.
// Zero-initialized statics => first launch clean; last block resets via
// atomicExch so every graph replay starts clean (deterministic).
__device__ unsigned g_maxenc[NB * RR];   // max over bin of enc(s)
__device__ unsigned g_minenc[NB * RR];   // max over bin of enc(-s)  (= -min)
__device__ unsigned g_done;              // ticket counter for last-block epilogue

__device__ __forceinline__ unsigned enc_f(float v) {
    unsigned b = __float_as_uint(v);
    return (b & 0x80000000u) ? ~b : (b | 0x80000000u);
}
__device__ __forceinline__ float dec_f(unsigned u) {
    unsigned b = (u & 0x80000000u) ? (u & 0x7FFFFFFFu) : ~u;
    return __uint_as_float(b);
}

// ---------------------------------------------------------------------------
// Persistent fused kernel: compacted score GEMV + binned min/max pooling +
// last-block epilogue. Every warp static-strides over the compacted row
// index space k in [0, sum(L)) -> no dead warps, one wave.
// Dot product done in two half-passes of 8 batched float4 loads each to
// bound register pressure (x loads batched for MLP; w loads serial from L1).
// ---------------------------------------------------------------------------
__global__ __launch_bounds__(THREADS, MINBLOCKS) void weldon_kernel(
    const float* __restrict__ x,
    const float* __restrict__ w,
    const int* __restrict__ lengths,
    float* __restrict__ out)
{
    const unsigned FULL = 0xFFFFFFFFu;
    const int lane = threadIdx.x & 31;
    const int warp_id = (blockIdx.x * blockDim.x + threadIdx.x) >> 5;
    const int nwarps = (gridDim.x * blockDim.x) >> 5;

    // Per-lane clamped length + inclusive shfl-scan -> prefix in register p.
    int Ll = 0;
    if (lane < NB) {
        int v = lengths[lane];
        Ll = min(max(v, 1), TT);
    }
    int p = Ll;
#pragma unroll
    for (int off = 1; off < 32; off <<= 1) {
        int v = __shfl_up_sync(FULL, p, off);
        if (lane >= off) p += v;
    }
    const int S = __shfl_sync(FULL, p, 31);     // total live rows

    const float4* __restrict__ w4 = reinterpret_cast<const float4*>(w);

    for (int k = warp_id; k < S; k += nwarps) {
        // Map compacted index k -> (n, t), t < L[n].
        const unsigned bal = __ballot_sync(FULL, k < p);
        const int n = __ffs(bal) - 1;
        const int pn = __shfl_sync(FULL, p, n);
        const int Ln = __shfl_sync(FULL, Ll, n);
        const int t = k - (pn - Ln);

        const float4* __restrict__ row = reinterpret_cast<const float4*>(
            x + ((size_t)n * TT + t) * DD);

        float sum = 0.0f;
#pragma unroll
        for (int half = 0; half < 2; ++half) {
            float4 a[8];
#pragma unroll
            for (int i = 0; i < 8; ++i)
                a[i] = row[lane + (half * 8 + i) * 32];
#pragma unroll
            for (int i = 0; i < 8; ++i) {
                const float4 b = w4[lane + (half * 8 + i) * 32];
                sum = fmaf(a[i].x, b.x, sum);
                sum = fmaf(a[i].y, b.y, sum);
                sum = fmaf(a[i].z, b.z, sum);
                sum = fmaf(a[i].w, b.w, sum);
            }
        }
#pragma unroll
        for (int off = 16; off > 0; off >>= 1)
            sum += __shfl_xor_sync(FULL, sum, off);

        if (lane == 0) {
            const unsigned emax = enc_f(sum);
            const unsigned emin = enc_f(-sum);
#pragma unroll
            for (int r = 0; r < RR; ++r) {
                const int start = (r * Ln) / RR;
                const int end = ((r + 1) * Ln + (RR - 1)) / RR;
                if (t >= start && t < end) {
                    atomicMax(&g_maxenc[n * RR + r], emax);
                    atomicMax(&g_minenc[n * RR + r], emin);
                }
            }
        }
    }

    // One fence per warp: make this warp's reductions device-visible before
    // the block's ticket increment.
    if (lane == 0) __threadfence();
    __syncthreads();

    // Last-block epilogue.
    __shared__ bool s_last;
    if (threadIdx.x == 0) {
        unsigned ticket = atomicAdd(&g_done, 1u);
        s_last = (ticket == gridDim.x - 1);
    }
    __syncthreads();

    if (s_last) {
        const int tid = threadIdx.x;
        if (tid < NB) {
            float acc = 0.0f;
#pragma unroll
            for (int r = 0; r < RR; ++r) {
                // atomicExch: L2-coherent read of final value AND reset to 0
                // (= -inf) for the next graph replay.
                const float mx = dec_f(atomicExch(&g_maxenc[tid * RR + r], 0u));
                const float mn = -dec_f(atomicExch(&g_minenc[tid * RR + r], 0u));
                acc += mx + mn;
            }
            out[tid] = 1.0f / (1.0f + expf(-acc));
        }
        if (tid == 0) {
            g_done = 0u;   // reset ticket for next replay
        }
    }
}

// ---------------------------------------------------------------------------
// kernel_launch
// Inputs (metadata order): x (float32, N*T*D), lengths (int32, N), w (float32, D)
// Output: float32, N
// ---------------------------------------------------------------------------
extern "C" void kernel_launch(void* const* d_in, const int* in_sizes, int n_in,
                              void* d_out, int out_size)
{
    const float* x = (const float*)d_in[0];
    const int* lengths = (const int*)d_in[1];
    const float* w = (const float*)d_in[2];
    float* out = (float*)d_out;

    weldon_kernel<<<BLOCKS, THREADS>>>(x, w, lengths, out);
}

// round 17
// speedup vs baseline: 1.3877x; 1.3877x over previous
#include <cuda_runtime.h>
#include <cuda_bf16.h>
#include <cfloat>
#include <cstdint>

// Problem shape (fixed by the reference).
#define NB 32
#define TT 4000
#define DD 2048
#define RR 10

#define THREADS 256
#define WARPS_PER_BLOCK 8
#define TOTAL_WARPS (NB * TT)                      // worst case S = 128000
#define BLOCKS ((TOTAL_WARPS + WARPS_PER_BLOCK - 1) / WARPS_PER_BLOCK)

// Per-(n,r) pooling slots. Order-preserving float->uint encoding; 0 acts as -inf.
// Zero-initialized statics => first launch clean; last block resets via
// atomicExch so every graph replay starts clean (deterministic).
__device__ unsigned g_maxenc[NB * RR];   // max over bin of enc(s)
__device__ unsigned g_minenc[NB * RR];   // max over bin of enc(-s)  (= -min)
__device__ unsigned g_done;              // ticket counter for last-block epilogue

__device__ __forceinline__ unsigned enc_f(float v) {
    unsigned b = __float_as_uint(v);
    return (b & 0x80000000u) ? ~b : (b | 0x80000000u);
}
__device__ __forceinline__ float dec_f(unsigned u) {
    unsigned b = (u & 0x80000000u) ? (u & 0x7FFFFFFFu) : ~u;
    return __uint_as_float(b);
}

// ---------------------------------------------------------------------------
// Fused kernel: one warp per LIVE (compacted) row.
// warp_global = k in [0, S) maps to (n, t) with t < L[n] via a 32-wide
// prefix scan of lengths. Live warps are densely packed in leading blocks
// -> sequential HBM streaming; trailing blocks exit immediately.
// ---------------------------------------------------------------------------
__global__ __launch_bounds__(THREADS) void weldon_kernel(
    const float* __restrict__ x,
    const float* __restrict__ w,
    const int* __restrict__ lengths,
    float* __restrict__ out)
{
    const unsigned FULL = 0xFFFFFFFFu;
    const int lane = threadIdx.x & 31;
    const int k = (blockIdx.x * blockDim.x + threadIdx.x) >> 5;  // compacted row

    // Per-lane clamped length + inclusive shfl-scan.
    int Ll = 0;
    if (lane < NB) {
        int v = lengths[lane];
        Ll = min(max(v, 1), TT);
    }
    int p = Ll;
#pragma unroll
    for (int off = 1; off < 32; off <<= 1) {
        int v = __shfl_up_sync(FULL, p, off);
        if (lane >= off) p += v;
    }
    const int S = __shfl_sync(FULL, p, 31);     // total live rows

    if (k < S) {
        // Map compacted index k -> (n, t), t < L[n].
        const unsigned bal = __ballot_sync(FULL, k < p);
        const int n = __ffs(bal) - 1;
        const int pn = __shfl_sync(FULL, p, n);
        const int Ln = __shfl_sync(FULL, Ll, n);
        const int t = k - (pn - Ln);

        const float4* __restrict__ row = reinterpret_cast<const float4*>(
            x + ((size_t)n * TT + t) * DD);
        const float4* __restrict__ w4 = reinterpret_cast<const float4*>(w);

        float sum = 0.0f;
#pragma unroll
        for (int i = 0; i < 16; ++i) {
            const int idx = lane + i * 32;
            float4 a = row[idx];
            float4 b = w4[idx];
            sum = fmaf(a.x, b.x, sum);
            sum = fmaf(a.y, b.y, sum);
            sum = fmaf(a.z, b.z, sum);
            sum = fmaf(a.w, b.w, sum);
        }
#pragma unroll
        for (int off = 16; off > 0; off >>= 1)
            sum += __shfl_xor_sync(FULL, sum, off);

        if (lane == 0) {
            const unsigned emax = enc_f(sum);
            const unsigned emin = enc_f(-sum);
#pragma unroll
            for (int r = 0; r < RR; ++r) {
                const int start = (r * Ln) / RR;
                const int end = ((r + 1) * Ln + (RR - 1)) / RR;
                if (t >= start && t < end) {
                    atomicMax(&g_maxenc[n * RR + r], emax);
                    atomicMax(&g_minenc[n * RR + r], emin);
                }
            }
            // One fence per live warp: reductions device-visible before ticket.
            __threadfence();
        }
    }

    __syncthreads();

    // Last-block epilogue (every block takes a ticket, live or not).
    __shared__ bool s_last;
    if (threadIdx.x == 0) {
        unsigned ticket = atomicAdd(&g_done, 1u);
        s_last = (ticket == gridDim.x - 1);
    }
    __syncthreads();

    if (s_last) {
        const int tid = threadIdx.x;
        if (tid < NB) {
            float acc = 0.0f;
#pragma unroll
            for (int r = 0; r < RR; ++r) {
                // atomicExch: L2-coherent read of final value AND reset to 0
                // (= -inf) for the next graph replay.
                const float mx = dec_f(atomicExch(&g_maxenc[tid * RR + r], 0u));
                const float mn = -dec_f(atomicExch(&g_minenc[tid * RR + r], 0u));
                acc += mx + mn;
            }
            out[tid] = 1.0f / (1.0f + expf(-acc));
        }
        if (tid == 0) {
            g_done = 0u;   // reset ticket for next replay
        }
    }
}

// ---------------------------------------------------------------------------
// kernel_launch
// Inputs (metadata order): x (float32, N*T*D), lengths (int32, N), w (float32, D)
// Output: float32, N
// ---------------------------------------------------------------------------
extern "C" void kernel_launch(void* const* d_in, const int* in_sizes, int n_in,
                              void* d_out, int out_size)
{
    const float* x = (const float*)d_in[0];
    const int* lengths = (const int*)d_in[1];
    const float* w = (const float*)d_in[2];
    float* out = (float*)d_out;

    weldon_kernel<<<BLOCKS, THREADS>>>(x, w, lengths, out);
}